// round 1
// baseline (speedup 1.0000x reference)
#include <cuda_runtime.h>
#include <cstdint>

#define Tn 128
#define Bn 8
#define Sn 512
#define CLUSTER 16
#define ROWS_PER_CTA (Sn / CLUSTER)      // 32
#define NTHREADS 512
#define NWARPS (NTHREADS / 32)           // 16
#define TILE_FLOATS (ROWS_PER_CTA * Sn)  // 16384 floats = 64 KB
#define DEPTH 3
#define SMEM_DYN (DEPTH * TILE_FLOATS * 4)  // 196608 B

#define LOG2E 1.4426950408889634f
#define LN2   0.6931471805599453f

__device__ __forceinline__ float ex2f(float x) {
    float y; asm("ex2.approx.ftz.f32 %0, %1;" : "=f"(y) : "f"(x)); return y;
}
__device__ __forceinline__ float lg2f(float x) {
    float y; asm("lg2.approx.ftz.f32 %0, %1;" : "=f"(y) : "f"(x)); return y;
}
__device__ __forceinline__ void cp16(uint32_t dst, const float* src) {
    asm volatile("cp.async.cg.shared.global [%0], [%1], 16;"
                 :: "r"(dst), "l"((const void*)src));
}

__global__ void __launch_bounds__(NTHREADS, 1)
viterbi_kernel(const float* __restrict__ theta, float* __restrict__ out)
{
    extern __shared__ float tiles[];          // DEPTH * TILE_FLOATS
    __shared__ float Vb[2][Sn];               // double-buffered V (written by peers via DSMEM)
    __shared__ float VL[Sn];                  // (V - M) * log2e
    __shared__ float red[NWARPS];

    const int tid  = threadIdx.x;
    const int lane = tid & 31;
    const int wid  = tid >> 5;

    uint32_t rank;
    asm("mov.u32 %0, %%cluster_ctarank;" : "=r"(rank));
    const int b = blockIdx.x >> 4;            // 16 CTAs per cluster = 1 batch

    const size_t step_stride = (size_t)Bn * Sn * Sn;   // floats per timestep
    const float* base = theta + (size_t)b * Sn * Sn
                              + (size_t)rank * ROWS_PER_CTA * Sn;

    // init: V0 = 0 -> M = 0, VL = 0
    VL[tid] = 0.0f;
    float M = 0.0f;

    const uint32_t tiles_s = (uint32_t)__cvta_generic_to_shared(tiles);

    // prefetch timesteps 0 .. DEPTH-2
    #pragma unroll
    for (int p = 0; p < DEPTH - 1; ++p) {
        const float* src = base + (size_t)p * step_stride + tid * 4;
        uint32_t dst = tiles_s + (uint32_t)(p * TILE_FLOATS + tid * 4) * 4u;
        #pragma unroll
        for (int i = 0; i < TILE_FLOATS / (NTHREADS * 4); ++i)   // 8 iters
            cp16(dst + (uint32_t)i * (NTHREADS * 16), src + i * (NTHREADS * 4));
        asm volatile("cp.async.commit_group;");
    }
    __syncthreads();   // VL init visible

    for (int t = 0; t < Tn; ++t) {
        // prefetch step t+DEPTH-1, then wait for step t's tile
        const int pre = t + DEPTH - 1;
        if (pre < Tn) {
            const float* src = base + (size_t)pre * step_stride + tid * 4;
            uint32_t dst = tiles_s + (uint32_t)((pre % DEPTH) * TILE_FLOATS + tid * 4) * 4u;
            #pragma unroll
            for (int i = 0; i < TILE_FLOATS / (NTHREADS * 4); ++i)
                cp16(dst + (uint32_t)i * (NTHREADS * 16), src + i * (NTHREADS * 4));
            asm volatile("cp.async.commit_group;");
            asm volatile("cp.async.wait_group 2;");
        } else {
            asm volatile("cp.async.wait_group 0;");
        }
        __syncthreads();

        // ---- compute: warp `wid` owns rows 2*wid, 2*wid+1 of this CTA's 32 rows ----
        const float* cur = tiles + (t % DEPTH) * TILE_FLOATS;
        const int r0 = wid * 2;
        const float4* row0 = (const float4*)(cur + r0 * Sn);
        const float4* row1 = (const float4*)(cur + (r0 + 1) * Sn);
        const float4* vl4  = (const float4*)VL;

        float a0 = 0.f, a1 = 0.f, b0 = 0.f, b1 = 0.f;
        #pragma unroll
        for (int c = 0; c < 4; ++c) {
            const int idx = c * 32 + lane;
            float4 vl = vl4[idx];
            float4 ta = row0[idx];
            float4 tb = row1[idx];
            a0 += ex2f(fmaf(ta.x, LOG2E, vl.x));
            a1 += ex2f(fmaf(ta.y, LOG2E, vl.y));
            a0 += ex2f(fmaf(ta.z, LOG2E, vl.z));
            a1 += ex2f(fmaf(ta.w, LOG2E, vl.w));
            b0 += ex2f(fmaf(tb.x, LOG2E, vl.x));
            b1 += ex2f(fmaf(tb.y, LOG2E, vl.y));
            b0 += ex2f(fmaf(tb.z, LOG2E, vl.z));
            b1 += ex2f(fmaf(tb.w, LOG2E, vl.w));
        }
        float acc0 = a0 + a1;
        float acc1 = b0 + b1;
        #pragma unroll
        for (int o = 16; o > 0; o >>= 1) {
            acc0 += __shfl_xor_sync(0xffffffffu, acc0, o);
            acc1 += __shfl_xor_sync(0xffffffffu, acc1, o);
        }
        const float v0 = fmaf(lg2f(acc0), LN2, M);
        const float v1 = fmaf(lg2f(acc1), LN2, M);

        // ---- broadcast the 2 new V values to all 16 cluster CTAs (incl. self) ----
        const int gi = (int)rank * ROWS_PER_CTA + r0;
        const int nb = (t + 1) & 1;
        if (lane < CLUSTER) {
            uint32_t la = (uint32_t)__cvta_generic_to_shared(&Vb[nb][gi]);
            uint32_t ra;
            asm("mapa.shared::cluster.u32 %0, %1, %2;" : "=r"(ra) : "r"(la), "r"(lane));
            asm volatile("st.shared::cluster.v2.f32 [%0], {%1, %2};"
                         :: "r"(ra), "f"(v0), "f"(v1) : "memory");
        }

        asm volatile("barrier.cluster.arrive.aligned;" ::: "memory");
        asm volatile("barrier.cluster.wait.aligned;"   ::: "memory");

        // ---- recompute batch max M and VL from the freshly assembled V ----
        const float v = Vb[nb][tid];
        float m = v;
        #pragma unroll
        for (int o = 16; o > 0; o >>= 1)
            m = fmaxf(m, __shfl_xor_sync(0xffffffffu, m, o));
        if (lane == 0) red[wid] = m;
        __syncthreads();
        if (wid == 0) {
            float x = red[lane & (NWARPS - 1)];
            #pragma unroll
            for (int o = 8; o > 0; o >>= 1)
                x = fmaxf(x, __shfl_xor_sync(0xffffffffu, x, o));
            if (lane == 0) red[0] = x;
        }
        __syncthreads();
        M = red[0];
        VL[tid] = (v - M) * LOG2E;
        __syncthreads();
    }

    // ---- final: out[b] = M + ln2 * log2( sum_j exp2(VL[j]) ) (rank-0 CTA only) ----
    if (rank == 0) {
        float e = ex2f(VL[tid]);
        #pragma unroll
        for (int o = 16; o > 0; o >>= 1)
            e += __shfl_xor_sync(0xffffffffu, e, o);
        if (lane == 0) red[wid] = e;
        __syncthreads();
        if (tid == 0) {
            float s = 0.f;
            #pragma unroll
            for (int i = 0; i < NWARPS; ++i) s += red[i];
            out[b] = fmaf(lg2f(s), LN2, M);
        }
    }
}

extern "C" void kernel_launch(void* const* d_in, const int* in_sizes, int n_in,
                              void* d_out, int out_size)
{
    const float* theta = (const float*)d_in[0];
    float* out = (float*)d_out;

    cudaFuncSetAttribute(viterbi_kernel,
                         cudaFuncAttributeMaxDynamicSharedMemorySize, SMEM_DYN);
    cudaFuncSetAttribute(viterbi_kernel,
                         cudaFuncAttributeNonPortableClusterSizeAllowed, 1);

    cudaLaunchConfig_t cfg = {};
    cfg.gridDim = dim3(Bn * CLUSTER, 1, 1);   // 128 CTAs
    cfg.blockDim = dim3(NTHREADS, 1, 1);
    cfg.dynamicSmemBytes = SMEM_DYN;
    cfg.stream = 0;

    cudaLaunchAttribute attrs[1];
    attrs[0].id = cudaLaunchAttributeClusterDimension;
    attrs[0].val.clusterDim.x = CLUSTER;
    attrs[0].val.clusterDim.y = 1;
    attrs[0].val.clusterDim.z = 1;
    cfg.attrs = attrs;
    cfg.numAttrs = 1;

    cudaLaunchKernelEx(&cfg, viterbi_kernel, theta, out);
}

// round 3
// speedup vs baseline: 1.3111x; 1.3111x over previous
#include <cuda_runtime.h>
#include <cstdint>

#define Tn 128
#define Bn 8
#define Sn 512
#define CLUSTER 16
#define ROWS_PER_CTA (Sn / CLUSTER)      // 32
#define NTHREADS 512
#define NWARPS (NTHREADS / 32)           // 16
#define TILE_FLOATS (ROWS_PER_CTA * Sn)  // 16384 floats = 64 KB
#define TILE_BYTES (TILE_FLOATS * 4)     // 65536
#define DEPTH 3
#define SMEM_DYN (DEPTH * TILE_BYTES)    // 196608 B

#define LOG2E 1.4426950408889634f
#define LN2   0.6931471805599453f

__device__ __forceinline__ float ex2f(float x) {
    float y; asm("ex2.approx.ftz.f32 %0, %1;" : "=f"(y) : "f"(x)); return y;
}
__device__ __forceinline__ float lg2f(float x) {
    float y; asm("lg2.approx.ftz.f32 %0, %1;" : "=f"(y) : "f"(x)); return y;
}

__device__ __forceinline__ void mbar_init(uint32_t mb, uint32_t count) {
    asm volatile("mbarrier.init.shared.b64 [%0], %1;" :: "r"(mb), "r"(count) : "memory");
}
__device__ __forceinline__ void mbar_expect_tx(uint32_t mb, uint32_t bytes) {
    asm volatile("mbarrier.arrive.expect_tx.shared.b64 _, [%0], %1;"
                 :: "r"(mb), "r"(bytes) : "memory");
}
__device__ __forceinline__ void bulk_ld(uint32_t dst, const void* src,
                                        uint32_t bytes, uint32_t mb) {
    asm volatile("cp.async.bulk.shared::cluster.global.mbarrier::complete_tx::bytes "
                 "[%0], [%1], %2, [%3];"
                 :: "r"(dst), "l"(src), "r"(bytes), "r"(mb) : "memory");
}
__device__ __forceinline__ void mbar_wait(uint32_t mb, uint32_t parity) {
    uint32_t done = 0;
    while (!done) {
        asm volatile(
            "{\n\t.reg .pred p;\n\t"
            "mbarrier.try_wait.parity.acquire.cta.shared::cta.b64 p, [%1], %2, 0x989680;\n\t"
            "selp.b32 %0, 1, 0, p;\n\t}"
            : "=r"(done) : "r"(mb), "r"(parity) : "memory");
    }
}

__global__ void __launch_bounds__(NTHREADS, 1)
viterbi_kernel(const float* __restrict__ theta, float* __restrict__ out)
{
    extern __shared__ float tiles[];                     // DEPTH * TILE_FLOATS
    __shared__ float Vb[2][Sn];                          // double-buffered V (DSMEM targets)
    __shared__ float VL[Sn];                             // (V - M) * log2e
    __shared__ float red[NWARPS];
    __shared__ __align__(8) unsigned long long mbar[DEPTH];

    const int tid  = threadIdx.x;
    const int lane = tid & 31;
    const int wid  = tid >> 5;

    uint32_t rank;
    asm("mov.u32 %0, %%cluster_ctarank;" : "=r"(rank));
    const int b = blockIdx.x >> 4;                       // 16 CTAs per cluster = 1 batch

    const size_t step_stride = (size_t)Bn * Sn * Sn;     // floats per timestep
    const float* base = theta + (size_t)b * Sn * Sn
                              + (size_t)rank * ROWS_PER_CTA * Sn;

    const uint32_t tiles_s = (uint32_t)__cvta_generic_to_shared(tiles);
    const uint32_t mbar_s  = (uint32_t)__cvta_generic_to_shared(&mbar[0]);

    // init
    VL[tid] = 0.0f;
    float M = 0.0f;
    if (tid == 0) {
        #pragma unroll
        for (int s = 0; s < DEPTH; ++s) mbar_init(mbar_s + 8u * s, 1);
    }
    __syncthreads();
    // fence so the async proxy (TMA) observes the mbarrier init
    asm volatile("fence.proxy.async.shared::cta;" ::: "memory");

    // prefetch timesteps 0 .. DEPTH-2
    if (tid == 0) {
        #pragma unroll
        for (int p = 0; p < DEPTH - 1; ++p) {
            mbar_expect_tx(mbar_s + 8u * p, TILE_BYTES);
            bulk_ld(tiles_s + (uint32_t)p * TILE_BYTES,
                    base + (size_t)p * step_stride, TILE_BYTES, mbar_s + 8u * p);
        }
    }

    for (int t = 0; t < Tn; ++t) {
        // prefetch step t+DEPTH-1 into its (now free) buffer
        const int pre = t + DEPTH - 1;
        if (pre < Tn && tid == 0) {
            const int pb = pre % DEPTH;
            mbar_expect_tx(mbar_s + 8u * pb, TILE_BYTES);
            bulk_ld(tiles_s + (uint32_t)pb * TILE_BYTES,
                    base + (size_t)pre * step_stride, TILE_BYTES, mbar_s + 8u * pb);
        }

        // wait for step t's tile
        const int cb = t % DEPTH;
        mbar_wait(mbar_s + 8u * cb, (uint32_t)((t / DEPTH) & 1));

        // ---- compute: warp `wid` owns rows 2*wid, 2*wid+1 of this CTA's 32 rows ----
        const float* cur = tiles + cb * TILE_FLOATS;
        const int r0 = wid * 2;
        const float4* row0 = (const float4*)(cur + r0 * Sn);
        const float4* row1 = (const float4*)(cur + (r0 + 1) * Sn);
        const float4* vl4  = (const float4*)VL;

        float a0 = 0.f, a1 = 0.f, b0 = 0.f, b1 = 0.f;
        #pragma unroll
        for (int c = 0; c < 4; ++c) {
            const int idx = c * 32 + lane;
            float4 vl = vl4[idx];
            float4 ta = row0[idx];
            float4 tb = row1[idx];
            a0 += ex2f(fmaf(ta.x, LOG2E, vl.x));
            a1 += ex2f(fmaf(ta.y, LOG2E, vl.y));
            a0 += ex2f(fmaf(ta.z, LOG2E, vl.z));
            a1 += ex2f(fmaf(ta.w, LOG2E, vl.w));
            b0 += ex2f(fmaf(tb.x, LOG2E, vl.x));
            b1 += ex2f(fmaf(tb.y, LOG2E, vl.y));
            b0 += ex2f(fmaf(tb.z, LOG2E, vl.z));
            b1 += ex2f(fmaf(tb.w, LOG2E, vl.w));
        }
        float acc0 = a0 + a1;
        float acc1 = b0 + b1;
        #pragma unroll
        for (int o = 16; o > 0; o >>= 1) {
            acc0 += __shfl_xor_sync(0xffffffffu, acc0, o);
            acc1 += __shfl_xor_sync(0xffffffffu, acc1, o);
        }
        const float v0 = fmaf(lg2f(acc0), LN2, M);
        const float v1 = fmaf(lg2f(acc1), LN2, M);

        // ---- broadcast the 2 new V values to all 16 cluster CTAs (incl. self) ----
        const int gi = (int)rank * ROWS_PER_CTA + r0;
        const int nb = (t + 1) & 1;
        if (lane < CLUSTER) {
            uint32_t la = (uint32_t)__cvta_generic_to_shared(&Vb[nb][gi]);
            uint32_t ra;
            asm("mapa.shared::cluster.u32 %0, %1, %2;" : "=r"(ra) : "r"(la), "r"(lane));
            asm volatile("st.shared::cluster.v2.f32 [%0], {%1, %2};"
                         :: "r"(ra), "f"(v0), "f"(v1) : "memory");
        }

        asm volatile("barrier.cluster.arrive.aligned;" ::: "memory");
        asm volatile("barrier.cluster.wait.aligned;"   ::: "memory");

        // ---- shift by V[0] (logsumexp is shift-invariant; spread is tiny) ----
        const float v  = Vb[nb][tid];
        const float Mn = Vb[nb][0];
        VL[tid] = (v - Mn) * LOG2E;
        M = Mn;
        __syncthreads();
    }

    // ---- final: out[b] = M + ln2 * log2( sum_j exp2(VL[j]) ) (rank-0 CTA only) ----
    if (rank == 0) {
        float e = ex2f(VL[tid]);
        #pragma unroll
        for (int o = 16; o > 0; o >>= 1)
            e += __shfl_xor_sync(0xffffffffu, e, o);
        if (lane == 0) red[wid] = e;
        __syncthreads();
        if (tid == 0) {
            float s = 0.f;
            #pragma unroll
            for (int i = 0; i < NWARPS; ++i) s += red[i];
            out[b] = fmaf(lg2f(s), LN2, M);
        }
    }
}

extern "C" void kernel_launch(void* const* d_in, const int* in_sizes, int n_in,
                              void* d_out, int out_size)
{
    const float* theta = (const float*)d_in[0];
    float* out = (float*)d_out;

    cudaFuncSetAttribute(viterbi_kernel,
                         cudaFuncAttributeMaxDynamicSharedMemorySize, SMEM_DYN);
    cudaFuncSetAttribute(viterbi_kernel,
                         cudaFuncAttributeNonPortableClusterSizeAllowed, 1);

    cudaLaunchConfig_t cfg = {};
    cfg.gridDim = dim3(Bn * CLUSTER, 1, 1);   // 128 CTAs
    cfg.blockDim = dim3(NTHREADS, 1, 1);
    cfg.dynamicSmemBytes = SMEM_DYN;
    cfg.stream = 0;

    cudaLaunchAttribute attrs[1];
    attrs[0].id = cudaLaunchAttributeClusterDimension;
    attrs[0].val.clusterDim.x = CLUSTER;
    attrs[0].val.clusterDim.y = 1;
    attrs[0].val.clusterDim.z = 1;
    cfg.attrs = attrs;
    cfg.numAttrs = 1;

    cudaLaunchKernelEx(&cfg, viterbi_kernel, theta, out);
}